// round 1
// baseline (speedup 1.0000x reference)
#include <cuda_runtime.h>
#include <math.h>

// Problem constants (fixed shapes for this registry problem)
#define N_NODES 50000
#define N_EDGES 800000
#define N_ET    (N_EDGES + N_NODES)   // with self loops = 850000
#define FDIM    256                   // H*C
#define F_IN    128
#define NH      4
#define NC      64
#define NB      64
#define NOUT    16
#define NHID    192

// ---------------- scratch (static device globals; no allocation allowed) ----
__device__ float g_lin[N_NODES * FDIM];   // post-GEMM features for current layer
__device__ float g_acc[N_NODES * FDIM];   // unnormalized message accumulator
__device__ float g_h  [N_NODES * FDIM];   // layer output (tanh), next layer input
__device__ float g_asrc[N_NODES * NH];
__device__ float g_adst[N_NODES * NH];
__device__ float g_m   [N_NODES * NH];    // segment max
__device__ float g_den [N_NODES * NH];    // segment sum of exp
__device__ float g_gmax[NB * NC];
__device__ float g_gsum[NB * NC];
__device__ float g_gcnt[NB];

__device__ __forceinline__ float atomicMaxFloat(float* addr, float value) {
    int* ia = (int*)addr;
    int old = *ia;
    while (__int_as_float(old) < value) {
        int assumed = old;
        old = atomicCAS(ia, assumed, __float_as_int(value));
        if (old == assumed) break;
    }
    return __int_as_float(old);
}

// ---------------- GEMM: C[M,256] = A[M,K] @ B[K,256]  (fp32, smem tiled) ----
#define BM 64
#define BN 64
#define BK 16
__global__ void k_gemm(const float* __restrict__ A, const float* __restrict__ B,
                       float* __restrict__ C, int M, int K) {
    __shared__ float As[BK][BM + 1];
    __shared__ float Bs[BK][BN];
    int tid = threadIdx.x;
    int tx = tid & 15, ty = tid >> 4;
    int m0 = blockIdx.y * BM;
    int n0 = blockIdx.x * BN;
    float acc[4][4] = {};

    int arow  = tid >> 2;         // 0..63
    int acol4 = (tid & 3) * 4;    // 0,4,8,12
    int brow  = tid >> 4;         // 0..15
    int bcol  = (tid & 15) * 4;   // 0..60

    for (int k0 = 0; k0 < K; k0 += BK) {
        float4 av = make_float4(0.f, 0.f, 0.f, 0.f);
        if (m0 + arow < M)
            av = *(const float4*)(A + (size_t)(m0 + arow) * K + k0 + acol4);
        As[acol4 + 0][arow] = av.x;
        As[acol4 + 1][arow] = av.y;
        As[acol4 + 2][arow] = av.z;
        As[acol4 + 3][arow] = av.w;

        float4 bv = *(const float4*)(B + (size_t)(k0 + brow) * FDIM + n0 + bcol);
        *(float4*)&Bs[brow][bcol] = bv;
        __syncthreads();

        #pragma unroll
        for (int k = 0; k < BK; k++) {
            float ar[4];
            #pragma unroll
            for (int i = 0; i < 4; i++) ar[i] = As[k][ty * 4 + i];
            float4 b4 = *(float4*)&Bs[k][tx * 4];
            float br[4] = {b4.x, b4.y, b4.z, b4.w};
            #pragma unroll
            for (int i = 0; i < 4; i++)
                #pragma unroll
                for (int j = 0; j < 4; j++)
                    acc[i][j] += ar[i] * br[j];
        }
        __syncthreads();
    }

    #pragma unroll
    for (int i = 0; i < 4; i++) {
        int m = m0 + ty * 4 + i;
        if (m < M) {
            float4 o = make_float4(acc[i][0], acc[i][1], acc[i][2], acc[i][3]);
            *(float4*)(C + (size_t)m * FDIM + n0 + tx * 4) = o;
        }
    }
}

// -------- attention coefficients: a_src[n,h], a_dst[n,h] --------------------
__global__ void k_att(const float* __restrict__ att_s, const float* __restrict__ att_d) {
    int i = blockIdx.x * blockDim.x + threadIdx.x;
    if (i >= N_NODES * NH) return;
    int n = i / NH, hh = i % NH;
    const float* row = g_lin + (size_t)n * FDIM + hh * NC;
    const float* as = att_s + hh * NC;
    const float* ad = att_d + hh * NC;
    float s = 0.f, d = 0.f;
    #pragma unroll 8
    for (int c = 0; c < NC; c++) {
        float v = row[c];
        s += v * as[c];
        d += v * ad[c];
    }
    g_asrc[i] = s;
    g_adst[i] = d;
}

// -------- init per-layer stats + accumulator --------------------------------
__global__ void k_init() {
    int i = blockIdx.x * blockDim.x + threadIdx.x;
    if (i < N_NODES * FDIM) g_acc[i] = 0.f;
    if (i < N_NODES * NH) { g_m[i] = -INFINITY; g_den[i] = 0.f; }
}

// -------- edge pass A: segment max of leaky-relu scores ---------------------
__global__ void k_edge_max(const int* __restrict__ src, const int* __restrict__ dst) {
    int i = blockIdx.x * blockDim.x + threadIdx.x;
    if (i >= N_ET * NH) return;
    int e = i >> 2, hh = i & 3;
    int s, d;
    if (e < N_EDGES) { s = src[e]; d = dst[e]; }
    else             { s = d = e - N_EDGES; }
    float ev = g_asrc[s * NH + hh] + g_adst[d * NH + hh];
    ev = ev > 0.f ? ev : 0.2f * ev;
    atomicMaxFloat(&g_m[d * NH + hh], ev);
}

// -------- edge pass B: exp, denom, unnormalized message accumulate ----------
// one warp per edge; 256 floats (64 float4) per edge split as 2 float4/lane
__global__ void k_edge_msg(const int* __restrict__ src, const int* __restrict__ dst) {
    int warp = (blockIdx.x * blockDim.x + threadIdx.x) >> 5;
    int lane = threadIdx.x & 31;
    if (warp >= N_ET) return;
    int s, d;
    if (warp < N_EDGES) { s = src[warp]; d = dst[warp]; }
    else                { s = d = warp - N_EDGES; }

    float ex[NH];
    #pragma unroll
    for (int hh = 0; hh < NH; hh++) {
        float ev = g_asrc[s * NH + hh] + g_adst[d * NH + hh];
        ev = ev > 0.f ? ev : 0.2f * ev;
        ex[hh] = expf(ev - g_m[d * NH + hh]);
    }
    if (lane < NH) atomicAdd(&g_den[d * NH + lane], ex[lane]);

    const float4* hs = (const float4*)(g_lin + (size_t)s * FDIM);
    float* ac = g_acc + (size_t)d * FDIM;
    #pragma unroll
    for (int r = 0; r < 2; r++) {
        int q = lane + r * 32;        // float4 index 0..63
        float4 v = hs[q];
        float xx = ex[q >> 4];        // head = (q*4)/64
        float* dp = ac + q * 4;
        atomicAdd(dp + 0, v.x * xx);
        atomicAdd(dp + 1, v.y * xx);
        atomicAdd(dp + 2, v.z * xx);
        atomicAdd(dp + 3, v.w * xx);
    }
}

// -------- finalize layer: normalize + bias + tanh ---------------------------
__global__ void k_finalize(const float* __restrict__ bias) {
    int i = blockIdx.x * blockDim.x + threadIdx.x;
    if (i >= N_NODES * FDIM) return;
    int n = i >> 8, j = i & 255;
    float den = g_den[n * NH + (j >> 6)];
    float v = g_acc[i] / (den + 1e-16f) + bias[j];
    g_h[i] = tanhf(v);
}

// -------- pooling -----------------------------------------------------------
__global__ void k_pool_init() {
    int i = blockIdx.x * blockDim.x + threadIdx.x;
    if (i < NB * NC) { g_gmax[i] = -INFINITY; g_gsum[i] = 0.f; }
    if (i < NB) g_gcnt[i] = 0.f;
}

__global__ void k_pool(const int* __restrict__ batch) {
    int i = blockIdx.x * blockDim.x + threadIdx.x;
    if (i >= N_NODES * NC) return;
    int n = i >> 6, c = i & 63;
    const float* row = g_h + (size_t)n * FDIM;
    float v = 0.25f * (row[c] + row[NC + c] + row[2 * NC + c] + row[3 * NC + c]);
    int b = batch[n];
    atomicMaxFloat(&g_gmax[b * NC + c], v);
    atomicAdd(&g_gsum[b * NC + c], v);
    if (c == 0) atomicAdd(&g_gcnt[b], 1.f);
}

// -------- output head: hidden = [gmax|gmean|gsum], out = hidden@Wout + bout -
__global__ void k_out(const float* __restrict__ Wout, const float* __restrict__ bout,
                      float* __restrict__ out) {
    __shared__ float hid[NHID];
    int b = blockIdx.x, t = threadIdx.x;
    float v;
    if (t < 64)       v = g_gmax[b * NC + t];
    else if (t < 128) v = g_gsum[b * NC + (t - 64)] / fmaxf(g_gcnt[b], 1.f);
    else              v = g_gsum[b * NC + (t - 128)];
    hid[t] = v;
    out[NB * NOUT + b * NHID + t] = v;   // hidden goes after out in d_out
    __syncthreads();
    if (t < NOUT) {
        float s = bout[t];
        #pragma unroll 8
        for (int k = 0; k < NHID; k++) s += hid[k] * Wout[k * NOUT + t];
        out[b * NOUT + t] = s;
    }
}

// ---------------------------------------------------------------------------
extern "C" void kernel_launch(void* const* d_in, const int* in_sizes, int n_in,
                              void* d_out, int out_size) {
    const float* x     = (const float*)d_in[0];
    const int*   ei    = (const int*)d_in[1];
    const int*   batch = (const int*)d_in[2];
    const float* W[3]  = {(const float*)d_in[3],  (const float*)d_in[7],  (const float*)d_in[11]};
    const float* Aslr[3] = {(const float*)d_in[4],  (const float*)d_in[8],  (const float*)d_in[12]};
    const float* Adlr[3] = {(const float*)d_in[5],  (const float*)d_in[9],  (const float*)d_in[13]};
    const float* Blr[3]  = {(const float*)d_in[6],  (const float*)d_in[10], (const float*)d_in[14]};
    const float* Wout  = (const float*)d_in[15];
    const float* bout  = (const float*)d_in[16];
    float* out = (float*)d_out;

    float *hbuf, *linbuf;
    cudaGetSymbolAddress((void**)&hbuf, g_h);
    cudaGetSymbolAddress((void**)&linbuf, g_lin);

    const int* srcp = ei;             // edge_index row 0
    const int* dstp = ei + N_EDGES;   // edge_index row 1

    for (int L = 0; L < 3; L++) {
        const float* hin = (L == 0) ? x : hbuf;
        int K = (L == 0) ? F_IN : FDIM;

        dim3 grid(FDIM / BN, (N_NODES + BM - 1) / BM);
        k_gemm<<<grid, 256>>>(hin, W[L], linbuf, N_NODES, K);

        k_att<<<(N_NODES * NH + 255) / 256, 256>>>(Aslr[L], Adlr[L]);
        k_init<<<(N_NODES * FDIM + 255) / 256, 256>>>();
        k_edge_max<<<(N_ET * NH + 255) / 256, 256>>>(srcp, dstp);
        k_edge_msg<<<((size_t)N_ET * 32 + 255) / 256, 256>>>(srcp, dstp);
        k_finalize<<<(N_NODES * FDIM + 255) / 256, 256>>>(Blr[L]);
    }

    k_pool_init<<<(NB * NC + 63) / 64, 64>>>();
    k_pool<<<(N_NODES * NC + 255) / 256, 256>>>(batch);
    k_out<<<NB, NHID>>>(Wout, bout, out);
}

// round 2
// speedup vs baseline: 2.2154x; 2.2154x over previous
#include <cuda_runtime.h>
#include <math.h>

// Problem constants (fixed shapes for this registry problem)
#define N_NODES 50000
#define N_EDGES 800000
#define N_ET    (N_EDGES + N_NODES)   // with self loops = 850000
#define FDIM    256                   // H*C
#define F_IN    128
#define NH      4
#define NC      64
#define NB      64
#define NOUT    16
#define NHID    192

// ---------------- scratch (static device globals; no allocation allowed) ----
__device__ float g_lin[N_NODES * FDIM];   // post-GEMM features for current layer
__device__ float g_h  [N_NODES * FDIM];   // layer output (tanh), next layer input
__device__ float g_asrc[N_NODES * NH];
__device__ float g_adst[N_NODES * NH];
__device__ float g_gmax[NB * NC];
__device__ float g_gsum[NB * NC];
__device__ float g_gcnt[NB];

// CSR by destination (built once per launch; edges constant across layers)
__device__ int g_deg[N_NODES];
__device__ int g_rowptr[N_NODES + 1];
__device__ int g_cursor[N_NODES];
__device__ int g_esrc[N_ET];

__device__ __forceinline__ float atomicMaxFloat(float* addr, float value) {
    int* ia = (int*)addr;
    int old = *ia;
    while (__int_as_float(old) < value) {
        int assumed = old;
        old = atomicCAS(ia, assumed, __float_as_int(value));
        if (old == assumed) break;
    }
    return __int_as_float(old);
}

// ========================= CSR construction ================================
__global__ void k_zero_deg() {
    int i = blockIdx.x * blockDim.x + threadIdx.x;
    if (i < N_NODES) g_deg[i] = 0;
}

__global__ void k_count(const int* __restrict__ dst) {
    int e = blockIdx.x * blockDim.x + threadIdx.x;
    if (e >= N_ET) return;
    int d = (e < N_EDGES) ? dst[e] : (e - N_EDGES);
    atomicAdd(&g_deg[d], 1);
}

// single-block exclusive scan of g_deg -> g_rowptr (+ init g_cursor)
__global__ void k_scan() {
    const int T = 1024;
    __shared__ int tmp[T];
    int t = threadIdx.x;
    const int chunk = (N_NODES + T - 1) / T;
    int start = t * chunk;
    int end = start + chunk; if (end > N_NODES) end = N_NODES;
    int sum = 0;
    for (int i = start; i < end; i++) sum += g_deg[i];
    tmp[t] = sum;
    __syncthreads();
    for (int off = 1; off < T; off <<= 1) {
        int v = (t >= off) ? tmp[t - off] : 0;
        __syncthreads();
        tmp[t] += v;
        __syncthreads();
    }
    int run = tmp[t] - sum;   // exclusive prefix
    for (int i = start; i < end; i++) {
        g_rowptr[i] = run;
        g_cursor[i] = run;
        run += g_deg[i];
    }
    if (t == T - 1) g_rowptr[N_NODES] = run;
}

__global__ void k_scatter(const int* __restrict__ src, const int* __restrict__ dst) {
    int e = blockIdx.x * blockDim.x + threadIdx.x;
    if (e >= N_ET) return;
    int s, d;
    if (e < N_EDGES) { s = src[e]; d = dst[e]; }
    else             { s = d = e - N_EDGES; }
    int pos = atomicAdd(&g_cursor[d], 1);
    g_esrc[pos] = s;
}

// ============ GEMM: C[M,256] = A[M,K] @ B[K,256]  (fp32, 128x128x16) =======
#define GBM 128
#define GBN 128
#define GBK 16
__global__ __launch_bounds__(256) void k_gemm(const float* __restrict__ A,
                                              const float* __restrict__ B,
                                              float* __restrict__ C, int M, int K) {
    __shared__ float As[GBK][GBM];       // transposed A tile
    __shared__ float Bs[GBK][GBN + 8];
    int tid = threadIdx.x;
    int m0 = blockIdx.y * GBM;
    int n0 = blockIdx.x * GBN;

    int ar  = tid >> 2;         // 0..63 (row within tile; +64 for second)
    int ac4 = (tid & 3) * 4;    // 0,4,8,12
    int br  = tid >> 5;         // 0..7  (+8 for second)
    int bc  = (tid & 31) * 4;   // 0..124
    int ty = tid >> 4, tx = tid & 15;

    float acc[8][8] = {};

    for (int k0 = 0; k0 < K; k0 += GBK) {
        #pragma unroll
        for (int r = 0; r < 2; r++) {
            int row = ar + r * 64;
            float4 av = make_float4(0.f, 0.f, 0.f, 0.f);
            if (m0 + row < M)
                av = *(const float4*)(A + (size_t)(m0 + row) * K + k0 + ac4);
            As[ac4 + 0][row] = av.x;
            As[ac4 + 1][row] = av.y;
            As[ac4 + 2][row] = av.z;
            As[ac4 + 3][row] = av.w;
        }
        #pragma unroll
        for (int r = 0; r < 2; r++) {
            float4 bv = *(const float4*)(B + (size_t)(k0 + br + r * 8) * FDIM + n0 + bc);
            *(float4*)&Bs[br + r * 8][bc] = bv;
        }
        __syncthreads();

        #pragma unroll
        for (int k = 0; k < GBK; k++) {
            float a[8], b[8];
            *(float4*)&a[0] = *(const float4*)&As[k][ty * 8];
            *(float4*)&a[4] = *(const float4*)&As[k][ty * 8 + 4];
            *(float4*)&b[0] = *(const float4*)&Bs[k][tx * 8];
            *(float4*)&b[4] = *(const float4*)&Bs[k][tx * 8 + 4];
            #pragma unroll
            for (int i = 0; i < 8; i++)
                #pragma unroll
                for (int j = 0; j < 8; j++)
                    acc[i][j] += a[i] * b[j];
        }
        __syncthreads();
    }

    #pragma unroll
    for (int i = 0; i < 8; i++) {
        int m = m0 + ty * 8 + i;
        if (m < M) {
            *(float4*)(C + (size_t)m * FDIM + n0 + tx * 8)     =
                make_float4(acc[i][0], acc[i][1], acc[i][2], acc[i][3]);
            *(float4*)(C + (size_t)m * FDIM + n0 + tx * 8 + 4) =
                make_float4(acc[i][4], acc[i][5], acc[i][6], acc[i][7]);
        }
    }
}

// -------- attention coefficients: a_src[n,h], a_dst[n,h] --------------------
__global__ void k_att(const float* __restrict__ att_s, const float* __restrict__ att_d) {
    int i = blockIdx.x * blockDim.x + threadIdx.x;
    if (i >= N_NODES * NH) return;
    int n = i / NH, hh = i % NH;
    const float* row = g_lin + (size_t)n * FDIM + hh * NC;
    const float* as = att_s + hh * NC;
    const float* ad = att_d + hh * NC;
    float s = 0.f, d = 0.f;
    #pragma unroll 8
    for (int c = 0; c < NC; c++) {
        float v = row[c];
        s += v * as[c];
        d += v * ad[c];
    }
    g_asrc[i] = s;
    g_adst[i] = d;
}

// ======= gather aggregation: one warp per destination node =================
// computes segment softmax + message accumulation + bias + tanh in one pass
__global__ __launch_bounds__(256) void k_agg(const float* __restrict__ bias) {
    int node = (blockIdx.x * blockDim.x + threadIdx.x) >> 5;
    int lane = threadIdx.x & 31;
    if (node >= N_NODES) return;
    int d = node;
    int r0 = g_rowptr[d], r1 = g_rowptr[d + 1];
    int hd = lane >> 3;                 // head owning this lane's 8 channels

    float4 ad4 = ((const float4*)g_adst)[d];
    float adv[4] = {ad4.x, ad4.y, ad4.z, ad4.w};

    // phase 1: per-head max of leaky-relu scores
    float mh[4] = {-INFINITY, -INFINITY, -INFINITY, -INFINITY};
    for (int i = r0 + lane; i < r1; i += 32) {
        int s = g_esrc[i];
        float4 as4 = ((const float4*)g_asrc)[s];
        float ev[4] = {as4.x + adv[0], as4.y + adv[1], as4.z + adv[2], as4.w + adv[3]};
        #pragma unroll
        for (int h = 0; h < 4; h++) {
            float e = ev[h] > 0.f ? ev[h] : 0.2f * ev[h];
            mh[h] = fmaxf(mh[h], e);
        }
    }
    #pragma unroll
    for (int off = 16; off; off >>= 1)
        #pragma unroll
        for (int h = 0; h < 4; h++)
            mh[h] = fmaxf(mh[h], __shfl_xor_sync(0xffffffffu, mh[h], off));

    // phase 2a: per-head denominator
    float den[4] = {0.f, 0.f, 0.f, 0.f};
    for (int i = r0 + lane; i < r1; i += 32) {
        int s = g_esrc[i];
        float4 as4 = ((const float4*)g_asrc)[s];
        float ev[4] = {as4.x + adv[0], as4.y + adv[1], as4.z + adv[2], as4.w + adv[3]};
        #pragma unroll
        for (int h = 0; h < 4; h++) {
            float e = ev[h] > 0.f ? ev[h] : 0.2f * ev[h];
            den[h] += expf(e - mh[h]);
        }
    }
    #pragma unroll
    for (int off = 16; off; off >>= 1)
        #pragma unroll
        for (int h = 0; h < 4; h++)
            den[h] += __shfl_xor_sync(0xffffffffu, den[h], off);

    // phase 2b: accumulate messages; each lane owns 8 channels (2 float4)
    float acc[8] = {};
    float mhd = mh[hd], adhd = adv[hd];
    int c0 = lane * 8;
    for (int i = r0; i < r1; i++) {
        int s = g_esrc[i];                       // warp-uniform load
        float e = g_asrc[s * NH + hd] + adhd;
        e = e > 0.f ? e : 0.2f * e;
        float ex = expf(e - mhd);
        const float4* hp = (const float4*)(g_lin + (size_t)s * FDIM + c0);
        float4 v0 = hp[0], v1 = hp[1];
        acc[0] += ex * v0.x; acc[1] += ex * v0.y;
        acc[2] += ex * v0.z; acc[3] += ex * v0.w;
        acc[4] += ex * v1.x; acc[5] += ex * v1.y;
        acc[6] += ex * v1.z; acc[7] += ex * v1.w;
    }

    float inv = 1.f / (den[hd] + 1e-16f);
    const float4* b4 = (const float4*)(bias + c0);
    float4 bb0 = b4[0], bb1 = b4[1];
    float4 o0, o1;
    o0.x = tanhf(acc[0] * inv + bb0.x);
    o0.y = tanhf(acc[1] * inv + bb0.y);
    o0.z = tanhf(acc[2] * inv + bb0.z);
    o0.w = tanhf(acc[3] * inv + bb0.w);
    o1.x = tanhf(acc[4] * inv + bb1.x);
    o1.y = tanhf(acc[5] * inv + bb1.y);
    o1.z = tanhf(acc[6] * inv + bb1.z);
    o1.w = tanhf(acc[7] * inv + bb1.w);
    float4* outp = (float4*)(g_h + (size_t)d * FDIM + c0);
    outp[0] = o0;
    outp[1] = o1;
}

// -------- pooling -----------------------------------------------------------
__global__ void k_pool_init() {
    int i = blockIdx.x * blockDim.x + threadIdx.x;
    if (i < NB * NC) { g_gmax[i] = -INFINITY; g_gsum[i] = 0.f; }
    if (i < NB) g_gcnt[i] = 0.f;
}

__global__ void k_pool(const int* __restrict__ batch) {
    int i = blockIdx.x * blockDim.x + threadIdx.x;
    if (i >= N_NODES * NC) return;
    int n = i >> 6, c = i & 63;
    const float* row = g_h + (size_t)n * FDIM;
    float v = 0.25f * (row[c] + row[NC + c] + row[2 * NC + c] + row[3 * NC + c]);
    int b = batch[n];
    atomicMaxFloat(&g_gmax[b * NC + c], v);
    atomicAdd(&g_gsum[b * NC + c], v);
    if (c == 0) atomicAdd(&g_gcnt[b], 1.f);
}

// -------- output head -------------------------------------------------------
__global__ void k_out(const float* __restrict__ Wout, const float* __restrict__ bout,
                      float* __restrict__ out) {
    __shared__ float hid[NHID];
    int b = blockIdx.x, t = threadIdx.x;
    float v;
    if (t < 64)       v = g_gmax[b * NC + t];
    else if (t < 128) v = g_gsum[b * NC + (t - 64)] / fmaxf(g_gcnt[b], 1.f);
    else              v = g_gsum[b * NC + (t - 128)];
    hid[t] = v;
    out[NB * NOUT + b * NHID + t] = v;   // hidden after out in d_out
    __syncthreads();
    if (t < NOUT) {
        float s = bout[t];
        #pragma unroll 8
        for (int k = 0; k < NHID; k++) s += hid[k] * Wout[k * NOUT + t];
        out[b * NOUT + t] = s;
    }
}

// ---------------------------------------------------------------------------
extern "C" void kernel_launch(void* const* d_in, const int* in_sizes, int n_in,
                              void* d_out, int out_size) {
    const float* x     = (const float*)d_in[0];
    const int*   ei    = (const int*)d_in[1];
    const int*   batch = (const int*)d_in[2];
    const float* W[3]    = {(const float*)d_in[3],  (const float*)d_in[7],  (const float*)d_in[11]};
    const float* Aslr[3] = {(const float*)d_in[4],  (const float*)d_in[8],  (const float*)d_in[12]};
    const float* Adlr[3] = {(const float*)d_in[5],  (const float*)d_in[9],  (const float*)d_in[13]};
    const float* Blr[3]  = {(const float*)d_in[6],  (const float*)d_in[10], (const float*)d_in[14]};
    const float* Wout  = (const float*)d_in[15];
    const float* bout  = (const float*)d_in[16];
    float* out = (float*)d_out;

    float *hbuf, *linbuf;
    cudaGetSymbolAddress((void**)&hbuf, g_h);
    cudaGetSymbolAddress((void**)&linbuf, g_lin);

    const int* srcp = ei;             // edge_index row 0
    const int* dstp = ei + N_EDGES;   // edge_index row 1

    // Build dst-CSR (edges constant across layers)
    k_zero_deg<<<(N_NODES + 255) / 256, 256>>>();
    k_count<<<(N_ET + 255) / 256, 256>>>(dstp);
    k_scan<<<1, 1024>>>();
    k_scatter<<<(N_ET + 255) / 256, 256>>>(srcp, dstp);

    for (int L = 0; L < 3; L++) {
        const float* hin = (L == 0) ? x : hbuf;
        int K = (L == 0) ? F_IN : FDIM;

        dim3 grid(FDIM / GBN, (N_NODES + GBM - 1) / GBM);
        k_gemm<<<grid, 256>>>(hin, W[L], linbuf, N_NODES, K);

        k_att<<<(N_NODES * NH + 255) / 256, 256>>>(Aslr[L], Adlr[L]);
        k_agg<<<(N_NODES * 32 + 255) / 256, 256>>>(Blr[L]);
    }

    k_pool_init<<<(NB * NC + 63) / 64, 64>>>();
    k_pool<<<(N_NODES * NC + 255) / 256, 256>>>(batch);
    k_out<<<NB, NHID>>>(Wout, bout, out);
}

// round 4
// speedup vs baseline: 3.1391x; 1.4170x over previous
#include <cuda_runtime.h>
#include <cuda_bf16.h>
#include <math.h>
#include <stdint.h>

// Problem constants
#define N_NODES 50000
#define N_EDGES 800000
#define N_ET    (N_EDGES + N_NODES)
#define FDIM    256
#define F_IN    128
#define NH      4
#define NC      64
#define NB      64
#define NOUT    16
#define NHID    192
#define KP_MAX  (3 * FDIM)      // 768

// ---------------- scratch ---------------------------------------------------
__device__ float g_lin[N_NODES * FDIM];
__device__ float g_h  [N_NODES * FDIM];
__device__ float g_asrc[N_NODES * NH];
__device__ float g_adst[N_NODES * NH];
__device__ float g_gmax[NB * NC];
__device__ float g_gsum[NB * NC];
__device__ float g_gcnt[NB];
__device__ __nv_bfloat16 g_abf[(size_t)N_NODES * KP_MAX];   // split-bf16 A'
__device__ __nv_bfloat16 g_bbf[FDIM * KP_MAX];              // split-bf16 B'

__device__ int g_deg[N_NODES];
__device__ int g_rowptr[N_NODES + 1];
__device__ int g_cursor[N_NODES];
__device__ int g_esrc[N_ET];

// ---------------- helpers ---------------------------------------------------
__device__ __forceinline__ uint32_t smem_u32(const void* p) {
    uint32_t a;
    asm("{ .reg .u64 t; cvta.to.shared.u64 t, %1; cvt.u32.u64 %0, t; }" : "=r"(a) : "l"(p));
    return a;
}
__device__ __forceinline__ void cp_async16(uint32_t dst, const void* src, bool pred) {
    int sz = pred ? 16 : 0;
    asm volatile("cp.async.cg.shared.global [%0], [%1], 16, %2;"
                 :: "r"(dst), "l"(src), "r"(sz) : "memory");
}
#define CP_COMMIT() asm volatile("cp.async.commit_group;" ::: "memory")
#define CP_WAIT(n)  asm volatile("cp.async.wait_group %0;" :: "n"(n) : "memory")

#define LDMATRIX_X4(r0, r1, r2, r3, addr) \
    asm volatile("ldmatrix.sync.aligned.m8n8.x4.shared.b16 {%0,%1,%2,%3}, [%4];" \
        : "=r"(r0), "=r"(r1), "=r"(r2), "=r"(r3) : "r"(addr))

#define MMA_BF16(c, a, b0, b1) \
    asm volatile("mma.sync.aligned.m16n8k16.row.col.f32.bf16.bf16.f32 " \
        "{%0,%1,%2,%3}, {%4,%5,%6,%7}, {%8,%9}, {%0,%1,%2,%3};" \
        : "+f"((c)[0]), "+f"((c)[1]), "+f"((c)[2]), "+f"((c)[3]) \
        : "r"((a)[0]), "r"((a)[1]), "r"((a)[2]), "r"((a)[3]), "r"(b0), "r"(b1))

__device__ __forceinline__ float atomicMaxFloat(float* addr, float value) {
    int* ia = (int*)addr;
    int old = *ia;
    while (__int_as_float(old) < value) {
        int assumed = old;
        old = atomicCAS(ia, assumed, __float_as_int(value));
        if (old == assumed) break;
    }
    return __int_as_float(old);
}

// ========================= CSR construction ================================
__global__ void k_zero_deg() {
    int i = blockIdx.x * blockDim.x + threadIdx.x;
    if (i < N_NODES) g_deg[i] = 0;
}
__global__ void k_count(const int* __restrict__ dst) {
    int e = blockIdx.x * blockDim.x + threadIdx.x;
    if (e >= N_ET) return;
    int d = (e < N_EDGES) ? dst[e] : (e - N_EDGES);
    atomicAdd(&g_deg[d], 1);
}
__global__ void k_scan() {
    const int T = 1024;
    __shared__ int tmp[T];
    int t = threadIdx.x;
    const int chunk = (N_NODES + T - 1) / T;
    int start = t * chunk;
    int end = start + chunk; if (end > N_NODES) end = N_NODES;
    int sum = 0;
    for (int i = start; i < end; i++) sum += g_deg[i];
    tmp[t] = sum;
    __syncthreads();
    for (int off = 1; off < T; off <<= 1) {
        int v = (t >= off) ? tmp[t - off] : 0;
        __syncthreads();
        tmp[t] += v;
        __syncthreads();
    }
    int run = tmp[t] - sum;
    for (int i = start; i < end; i++) {
        g_rowptr[i] = run;
        g_cursor[i] = run;
        run += g_deg[i];
    }
    if (t == T - 1) g_rowptr[N_NODES] = run;
}
__global__ void k_scatter(const int* __restrict__ src, const int* __restrict__ dst) {
    int e = blockIdx.x * blockDim.x + threadIdx.x;
    if (e >= N_ET) return;
    int s, d;
    if (e < N_EDGES) { s = src[e]; d = dst[e]; }
    else             { s = d = e - N_EDGES; }
    int pos = atomicAdd(&g_cursor[d], 1);
    g_esrc[pos] = s;
}

// ================= split-bf16 conversion ===================================
// A' = [A_hi | A_lo | A_hi], row-major [M, 3K]
__global__ void k_conv_a(const float* __restrict__ in, __nv_bfloat16* __restrict__ out,
                         int M, int K) {
    int K4 = K >> 2;
    int i = blockIdx.x * blockDim.x + threadIdx.x;
    if (i >= M * K4) return;
    int m = i / K4, k4 = (i - m * K4) << 2;
    int Kp = 3 * K;
    float4 v = *(const float4*)(in + (size_t)m * K + k4);
    float vv[4] = {v.x, v.y, v.z, v.w};
    __nv_bfloat16 hi[4], lo[4];
    #pragma unroll
    for (int j = 0; j < 4; j++) {
        hi[j] = __float2bfloat16(vv[j]);
        lo[j] = __float2bfloat16(vv[j] - __bfloat162float(hi[j]));
    }
    __nv_bfloat162 h01, h23, l01, l23;
    h01.x = hi[0]; h01.y = hi[1]; h23.x = hi[2]; h23.y = hi[3];
    l01.x = lo[0]; l01.y = lo[1]; l23.x = lo[2]; l23.y = lo[3];
    __nv_bfloat162* o0 = (__nv_bfloat162*)(out + (size_t)m * Kp + k4);
    __nv_bfloat162* o1 = (__nv_bfloat162*)(out + (size_t)m * Kp + K + k4);
    __nv_bfloat162* o2 = (__nv_bfloat162*)(out + (size_t)m * Kp + 2 * K + k4);
    o0[0] = h01; o0[1] = h23;
    o1[0] = l01; o1[1] = l23;
    o2[0] = h01; o2[1] = h23;
}

// B' = [B_hi | B_hi | B_lo], [N=256 rows, 3K] from W [K, 256]
__global__ void k_conv_b(const float* __restrict__ W, __nv_bfloat16* __restrict__ out, int K) {
    int i = blockIdx.x * blockDim.x + threadIdx.x;
    if (i >= K * FDIM) return;
    int n = i & (FDIM - 1), k = i >> 8;
    int Kp = 3 * K;
    float w = W[(size_t)k * FDIM + n];
    __nv_bfloat16 hi = __float2bfloat16(w);
    __nv_bfloat16 lo = __float2bfloat16(w - __bfloat162float(hi));
    out[(size_t)n * Kp + k] = hi;
    out[(size_t)n * Kp + K + k] = hi;
    out[(size_t)n * Kp + 2 * K + k] = lo;
}

// ====== HMMA GEMM: C[M,256] = A'[M,Kp] x B'[256,Kp]^T  + fused att =========
#define BM 128
#define BN 128
#define BK 32
#define PAD 8
#define LROW (BK + PAD)   // 40 bf16 per smem row

__global__ void __launch_bounds__(256)
k_gemm_mma(const __nv_bfloat16* __restrict__ A, const __nv_bfloat16* __restrict__ B,
           float* __restrict__ C, const float* __restrict__ atts,
           const float* __restrict__ attd, int M, int Kp) {
    __shared__ __align__(16) __nv_bfloat16 sA[2][BM * LROW];
    __shared__ __align__(16) __nv_bfloat16 sB[2][BN * LROW];
    __shared__ float attSs[FDIM], attDs[FDIM];

    int tid = threadIdx.x;
    int lane = tid & 31, wid = tid >> 5;
    int warpM = wid & 3;        // 4 warps along M (32 rows each)
    int warpN = wid >> 2;       // 2 warps along N (64 cols each)
    int m0 = blockIdx.y * BM;
    int n0 = blockIdx.x * BN;

    attSs[tid] = atts[tid];
    attDs[tid] = attd[tid];

    float acc[2][8][4];
    #pragma unroll
    for (int i = 0; i < 2; i++)
        #pragma unroll
        for (int j = 0; j < 8; j++)
            #pragma unroll
            for (int q = 0; q < 4; q++) acc[i][j][q] = 0.f;

    int ns = Kp / BK;
    int ldrow = tid >> 2;              // 0..63, +64 second half
    int ldc8  = (tid & 3) * 8;         // bf16 col offset

    // prefetch stage 0
    {
        uint32_t aB = smem_u32(sA[0]);
        uint32_t bB = smem_u32(sB[0]);
        #pragma unroll
        for (int r = 0; r < 2; r++) {
            int row = ldrow + r * 64;
            int gm = m0 + row;
            cp_async16(aB + (row * LROW + ldc8) * 2,
                       A + (size_t)gm * Kp + ldc8, gm < M);
            cp_async16(bB + (row * LROW + ldc8) * 2,
                       B + (size_t)(n0 + row) * Kp + ldc8, true);
        }
        CP_COMMIT();
    }

    for (int s = 0; s < ns; s++) {
        int buf = s & 1;
        if (s + 1 < ns) {
            int nb = 1 - buf;
            int k0 = (s + 1) * BK;
            uint32_t aB = smem_u32(sA[nb]);
            uint32_t bB = smem_u32(sB[nb]);
            #pragma unroll
            for (int r = 0; r < 2; r++) {
                int row = ldrow + r * 64;
                int gm = m0 + row;
                cp_async16(aB + (row * LROW + ldc8) * 2,
                           A + (size_t)gm * Kp + k0 + ldc8, gm < M);
                cp_async16(bB + (row * LROW + ldc8) * 2,
                           B + (size_t)(n0 + row) * Kp + k0 + ldc8, true);
            }
            CP_COMMIT();
            CP_WAIT(1);
        } else {
            CP_WAIT(0);
        }
        __syncthreads();

        uint32_t aB = smem_u32(sA[buf]);
        uint32_t bB = smem_u32(sB[buf]);
        #pragma unroll
        for (int ks = 0; ks < 2; ks++) {
            uint32_t a[2][4];
            #pragma unroll
            for (int mi = 0; mi < 2; mi++) {
                uint32_t ad = aB + (((warpM * 32 + mi * 16 + (lane & 15)) * LROW)
                                    + ks * 16 + ((lane >> 4) * 8)) * 2;
                LDMATRIX_X4(a[mi][0], a[mi][1], a[mi][2], a[mi][3], ad);
            }
            uint32_t b[4][4];
            #pragma unroll
            for (int ni = 0; ni < 4; ni++) {
                uint32_t bd = bB + (((warpN * 64 + ni * 16 + (lane & 15)) * LROW)
                                    + ks * 16 + ((lane >> 4) * 8)) * 2;
                LDMATRIX_X4(b[ni][0], b[ni][1], b[ni][2], b[ni][3], bd);
            }
            #pragma unroll
            for (int mi = 0; mi < 2; mi++)
                #pragma unroll
                for (int ni = 0; ni < 4; ni++) {
                    MMA_BF16(acc[mi][ni * 2],     a[mi], b[ni][0], b[ni][2]);
                    MMA_BF16(acc[mi][ni * 2 + 1], a[mi], b[ni][1], b[ni][3]);
                }
        }
        __syncthreads();
    }

    // ---------------- epilogue: store C + fused attention coefficients -----
    float sp[2][2] = {}, dp[2][2] = {};
    int qrow = lane >> 2;              // 0..7
    int qcol = (lane & 3) * 2;

    #pragma unroll
    for (int mi = 0; mi < 2; mi++) {
        int mA = m0 + warpM * 32 + mi * 16 + qrow;
        int mB2 = mA + 8;
        bool vA = (mA < M), vB = (mB2 < M);
        #pragma unroll
        for (int ni = 0; ni < 8; ni++) {
            int gcol = n0 + warpN * 64 + ni * 8 + qcol;
            float c0 = acc[mi][ni][0], c1 = acc[mi][ni][1];
            float c2 = acc[mi][ni][2], c3 = acc[mi][ni][3];
            float s0 = attSs[gcol], s1 = attSs[gcol + 1];
            float d0 = attDs[gcol], d1 = attDs[gcol + 1];
            sp[mi][0] += c0 * s0 + c1 * s1;
            sp[mi][1] += c2 * s0 + c3 * s1;
            dp[mi][0] += c0 * d0 + c1 * d1;
            dp[mi][1] += c2 * d0 + c3 * d1;
            if (vA) *(float2*)(C + (size_t)mA * FDIM + gcol) = make_float2(c0, c1);
            if (vB) *(float2*)(C + (size_t)mB2 * FDIM + gcol) = make_float2(c2, c3);
        }
    }
    // reduce over the 4 lanes sharing the same rows (lane%4 spans columns)
    #pragma unroll
    for (int off = 1; off <= 2; off <<= 1) {
        #pragma unroll
        for (int mi = 0; mi < 2; mi++)
            #pragma unroll
            for (int rp = 0; rp < 2; rp++) {
                sp[mi][rp] += __shfl_xor_sync(0xffffffffu, sp[mi][rp], off);
                dp[mi][rp] += __shfl_xor_sync(0xffffffffu, dp[mi][rp], off);
            }
    }
    if ((lane & 3) == 0) {
        int head = blockIdx.x * 2 + warpN;
        #pragma unroll
        for (int mi = 0; mi < 2; mi++)
            #pragma unroll
            for (int rp = 0; rp < 2; rp++) {
                int m = m0 + warpM * 32 + mi * 16 + qrow + rp * 8;
                if (m < M) {
                    g_asrc[m * NH + head] = sp[mi][rp];
                    g_adst[m * NH + head] = dp[mi][rp];
                }
            }
    }
}

// ======= gather aggregation: one warp per destination node =================
__global__ __launch_bounds__(256) void k_agg(const float* __restrict__ bias) {
    int node = (blockIdx.x * blockDim.x + threadIdx.x) >> 5;
    int lane = threadIdx.x & 31;
    if (node >= N_NODES) return;
    int d = node;
    int r0 = g_rowptr[d], r1 = g_rowptr[d + 1];
    int hd = lane >> 3;

    float4 ad4 = ((const float4*)g_adst)[d];
    float adv[4] = {ad4.x, ad4.y, ad4.z, ad4.w};

    float mh[4] = {-INFINITY, -INFINITY, -INFINITY, -INFINITY};
    for (int i = r0 + lane; i < r1; i += 32) {
        int s = g_esrc[i];
        float4 as4 = ((const float4*)g_asrc)[s];
        float ev[4] = {as4.x + adv[0], as4.y + adv[1], as4.z + adv[2], as4.w + adv[3]};
        #pragma unroll
        for (int h = 0; h < 4; h++) {
            float e = ev[h] > 0.f ? ev[h] : 0.2f * ev[h];
            mh[h] = fmaxf(mh[h], e);
        }
    }
    #pragma unroll
    for (int off = 16; off; off >>= 1)
        #pragma unroll
        for (int h = 0; h < 4; h++)
            mh[h] = fmaxf(mh[h], __shfl_xor_sync(0xffffffffu, mh[h], off));

    float den[4] = {0.f, 0.f, 0.f, 0.f};
    for (int i = r0 + lane; i < r1; i += 32) {
        int s = g_esrc[i];
        float4 as4 = ((const float4*)g_asrc)[s];
        float ev[4] = {as4.x + adv[0], as4.y + adv[1], as4.z + adv[2], as4.w + adv[3]};
        #pragma unroll
        for (int h = 0; h < 4; h++) {
            float e = ev[h] > 0.f ? ev[h] : 0.2f * ev[h];
            den[h] += expf(e - mh[h]);
        }
    }
    #pragma unroll
    for (int off = 16; off; off >>= 1)
        #pragma unroll
        for (int h = 0; h < 4; h++)
            den[h] += __shfl_xor_sync(0xffffffffu, den[h], off);

    float acc[8] = {};
    float mhd = mh[hd], adhd = adv[hd];
    int c0 = lane * 8;
    for (int i = r0; i < r1; i++) {
        int s = g_esrc[i];
        float e = g_asrc[s * NH + hd] + adhd;
        e = e > 0.f ? e : 0.2f * e;
        float ex = expf(e - mhd);
        const float4* hp = (const float4*)(g_lin + (size_t)s * FDIM + c0);
        float4 v0 = hp[0], v1 = hp[1];
        acc[0] += ex * v0.x; acc[1] += ex * v0.y;
        acc[2] += ex * v0.z; acc[3] += ex * v0.w;
        acc[4] += ex * v1.x; acc[5] += ex * v1.y;
        acc[6] += ex * v1.z; acc[7] += ex * v1.w;
    }

    float inv = 1.f / (den[hd] + 1e-16f);
    const float4* b4 = (const float4*)(bias + c0);
    float4 bb0 = b4[0], bb1 = b4[1];
    float4 o0, o1;
    o0.x = tanhf(acc[0] * inv + bb0.x);
    o0.y = tanhf(acc[1] * inv + bb0.y);
    o0.z = tanhf(acc[2] * inv + bb0.z);
    o0.w = tanhf(acc[3] * inv + bb0.w);
    o1.x = tanhf(acc[4] * inv + bb1.x);
    o1.y = tanhf(acc[5] * inv + bb1.y);
    o1.z = tanhf(acc[6] * inv + bb1.z);
    o1.w = tanhf(acc[7] * inv + bb1.w);
    float4* outp = (float4*)(g_h + (size_t)d * FDIM + c0);
    outp[0] = o0;
    outp[1] = o1;
}

// -------- pooling -----------------------------------------------------------
__global__ void k_pool_init() {
    int i = blockIdx.x * blockDim.x + threadIdx.x;
    if (i < NB * NC) { g_gmax[i] = -INFINITY; g_gsum[i] = 0.f; }
    if (i < NB) g_gcnt[i] = 0.f;
}
__global__ void k_pool(const int* __restrict__ batch) {
    int i = blockIdx.x * blockDim.x + threadIdx.x;
    if (i >= N_NODES * NC) return;
    int n = i >> 6, c = i & 63;
    const float* row = g_h + (size_t)n * FDIM;
    float v = 0.25f * (row[c] + row[NC + c] + row[2 * NC + c] + row[3 * NC + c]);
    int b = batch[n];
    atomicMaxFloat(&g_gmax[b * NC + c], v);
    atomicAdd(&g_gsum[b * NC + c], v);
    if (c == 0) atomicAdd(&g_gcnt[b], 1.f);
}
__global__ void k_out(const float* __restrict__ Wout, const float* __restrict__ bout,
                      float* __restrict__ out) {
    __shared__ float hid[NHID];
    int b = blockIdx.x, t = threadIdx.x;
    float v;
    if (t < 64)       v = g_gmax[b * NC + t];
    else if (t < 128) v = g_gsum[b * NC + (t - 64)] / fmaxf(g_gcnt[b], 1.f);
    else              v = g_gsum[b * NC + (t - 128)];
    hid[t] = v;
    out[NB * NOUT + b * NHID + t] = v;
    __syncthreads();
    if (t < NOUT) {
        float s = bout[t];
        #pragma unroll 8
        for (int k = 0; k < NHID; k++) s += hid[k] * Wout[k * NOUT + t];
        out[b * NOUT + t] = s;
    }
}

// ---------------------------------------------------------------------------
extern "C" void kernel_launch(void* const* d_in, const int* in_sizes, int n_in,
                              void* d_out, int out_size) {
    const float* x     = (const float*)d_in[0];
    const int*   ei    = (const int*)d_in[1];
    const int*   batch = (const int*)d_in[2];
    const float* W[3]    = {(const float*)d_in[3],  (const float*)d_in[7],  (const float*)d_in[11]};
    const float* Aslr[3] = {(const float*)d_in[4],  (const float*)d_in[8],  (const float*)d_in[12]};
    const float* Adlr[3] = {(const float*)d_in[5],  (const float*)d_in[9],  (const float*)d_in[13]};
    const float* Blr[3]  = {(const float*)d_in[6],  (const float*)d_in[10], (const float*)d_in[14]};
    const float* Wout  = (const float*)d_in[15];
    const float* bout  = (const float*)d_in[16];
    float* out = (float*)d_out;

    float *hbuf, *linbuf;
    __nv_bfloat16 *abf, *bbf;
    cudaGetSymbolAddress((void**)&hbuf, g_h);
    cudaGetSymbolAddress((void**)&linbuf, g_lin);
    cudaGetSymbolAddress((void**)&abf, g_abf);
    cudaGetSymbolAddress((void**)&bbf, g_bbf);

    const int* srcp = ei;
    const int* dstp = ei + N_EDGES;

    k_zero_deg<<<(N_NODES + 255) / 256, 256>>>();
    k_count<<<(N_ET + 255) / 256, 256>>>(dstp);
    k_scan<<<1, 1024>>>();
    k_scatter<<<(N_ET + 255) / 256, 256>>>(srcp, dstp);

    for (int L = 0; L < 3; L++) {
        const float* hin = (L == 0) ? x : hbuf;
        int K = (L == 0) ? F_IN : FDIM;
        int Kp = 3 * K;

        k_conv_a<<<(N_NODES * (K / 4) + 255) / 256, 256>>>(hin, abf, N_NODES, K);
        k_conv_b<<<(K * FDIM + 255) / 256, 256>>>(W[L], bbf, K);

        dim3 grid(FDIM / BN, (N_NODES + BM - 1) / BM);
        k_gemm_mma<<<grid, 256>>>(abf, bbf, linbuf, Aslr[L], Adlr[L], N_NODES, Kp);

        k_agg<<<(N_NODES * 32 + 255) / 256, 256>>>(Blr[L]);
    }

    k_pool_init<<<(NB * NC + 63) / 64, 64>>>();
    k_pool<<<(N_NODES * NC + 255) / 256, 256>>>(batch);
    k_out<<<NB, NHID>>>(Wout, bout, out);
}